// round 3
// baseline (speedup 1.0000x reference)
#include <cuda_runtime.h>

#define NN 50000
#define EE 1600000
#define EP (EE + NN)
#define GG 64
#define IND 128
#define HIDD 64

// ---------------- device scratch (no allocations allowed) ----------------
__device__ __align__(16) float g_xl[NN * HIDD];
__device__ __align__(16) float g_xr[NN * HIDD];
__device__ __align__(16) float g_h[NN * HIDD];
__device__ __align__(16) float g_accum[NN * HIDD];
__device__ float g_logits[EP];
__device__ float g_loop[NN];
__device__ float g_easum[NN];
__device__ float g_eacnt[NN];
__device__ unsigned g_maxkey[NN];
__device__ float g_denom[NN];
__device__ float g_pool[GG * HIDD];
__device__ float g_pcnt[GG];

// ordered-uint encoding for float atomicMax
__device__ __forceinline__ unsigned fkey(float f) {
    unsigned b = __float_as_uint(f);
    return (b & 0x80000000u) ? ~b : (b | 0x80000000u);
}
__device__ __forceinline__ float fdec(unsigned k) {
    return __uint_as_float((k & 0x80000000u) ? (k & 0x7FFFFFFFu) : ~k);
}

// ---------------- init ----------------
__global__ void init_graph_kernel() {
    int i = blockIdx.x * blockDim.x + threadIdx.x;
    if (i < NN) { g_easum[i] = 0.f; g_eacnt[i] = 0.f; }
    if (i < GG * HIDD) g_pool[i] = 0.f;
    if (i < GG) g_pcnt[i] = 0.f;
}

__global__ void init_layer_kernel() {
    int i = blockIdx.x * blockDim.x + threadIdx.x;
    if (i < NN * HIDD) g_accum[i] = 0.f;
    if (i < NN) { g_denom[i] = 0.f; g_maxkey[i] = 0u; }
}

// ---------------- self-loop attr (fill_value='mean') ----------------
__global__ void loop_accum_kernel(const int* __restrict__ ei, const float* __restrict__ ea) {
    int e = blockIdx.x * blockDim.x + threadIdx.x;
    if (e >= EE) return;
    int d = ei[EE + e];
    atomicAdd(&g_easum[d], ea[e]);
    atomicAdd(&g_eacnt[d], 1.f);
}

__global__ void loop_final_kernel() {
    int i = blockIdx.x * blockDim.x + threadIdx.x;
    if (i >= NN) return;
    g_loop[i] = g_easum[i] / fmaxf(g_eacnt[i], 1.f);
}

// ---------------- node linear transforms: xl = h@Wl+bl, xr = h@Wr+br ----------------
// blockDim = (64, 4): 4 nodes per block, thread.x = out channel
template <int K, bool FROM_H>
__global__ void linear_kernel(const float* __restrict__ x,
                              const float* __restrict__ Wl, const float* __restrict__ bl,
                              const float* __restrict__ Wr, const float* __restrict__ br) {
    __shared__ float sx[4][K];
    int node = blockIdx.x * 4 + threadIdx.y;
    int c = threadIdx.x;
    if (node < NN) {
        const float* src = FROM_H ? (g_h + node * K) : (x + node * K);
        for (int k = c; k < K; k += 64) sx[threadIdx.y][k] = src[k];
    }
    __syncthreads();
    if (node >= NN) return;
    float al = bl[c], ar = br[c];
#pragma unroll 8
    for (int k = 0; k < K; k++) {
        float xv = sx[threadIdx.y][k];
        al = fmaf(xv, Wl[k * 64 + c], al);
        ar = fmaf(xv, Wr[k * 64 + c], ar);
    }
    g_xl[node * 64 + c] = al;
    g_xr[node * 64 + c] = ar;
}

// ---------------- edge pass 1: logits + segment max ----------------
// one warp per edge, 2 channels per lane (float2)
__global__ void edge_logits_kernel(const int* __restrict__ ei, const float* __restrict__ ea,
                                   const float* __restrict__ We, const float* __restrict__ att) {
    int gtid = blockIdx.x * blockDim.x + threadIdx.x;
    int e = gtid >> 5, lane = gtid & 31;
    if (e >= EP) return;
    int s, d;
    float a;
    if (e < EE) { s = ei[e]; d = ei[EE + e]; a = ea[e]; }
    else { s = d = e - EE; a = g_loop[s]; }
    float2 xl = ((const float2*)g_xl)[s * 32 + lane];
    float2 xr = ((const float2*)g_xr)[d * 32 + lane];
    float2 w = ((const float2*)We)[lane];
    float2 at = ((const float2*)att)[lane];
    float v0 = xl.x + xr.x + a * w.x;
    v0 = v0 > 0.f ? v0 : 0.2f * v0;
    float v1 = xl.y + xr.y + a * w.y;
    v1 = v1 > 0.f ? v1 : 0.2f * v1;
    float sum = v0 * at.x + v1 * at.y;
#pragma unroll
    for (int o = 16; o; o >>= 1) sum += __shfl_xor_sync(0xffffffffu, sum, o);
    if (lane == 0) {
        g_logits[e] = sum;
        atomicMax(&g_maxkey[d], fkey(sum));
    }
}

// ---------------- edge pass 2: p = exp(l - m); accumulate numerator + denom ----------------
__global__ void edge_accum_kernel(const int* __restrict__ ei) {
    int gtid = blockIdx.x * blockDim.x + threadIdx.x;
    int e = gtid >> 5, lane = gtid & 31;
    if (e >= EP) return;
    int s, d;
    if (e < EE) { s = ei[e]; d = ei[EE + e]; }
    else { s = d = e - EE; }
    float m = fdec(g_maxkey[d]);
    float p = __expf(g_logits[e] - m);
    float2 xl = ((const float2*)g_xl)[s * 32 + lane];
    atomicAdd(&g_accum[d * 64 + 2 * lane], p * xl.x);
    atomicAdd(&g_accum[d * 64 + 2 * lane + 1], p * xl.y);
    if (lane == 0) atomicAdd(&g_denom[d], p);
}

// ---------------- node finalize: h = elu(accum/denom + bias); optional pooling ----------------
__global__ void node_final_kernel(const float* __restrict__ bias, const int* __restrict__ batch,
                                  int do_pool) {
    int i = blockIdx.x, c = threadIdx.x;
    float v = g_accum[i * 64 + c] / (g_denom[i] + 1e-16f) + bias[c];
    v = v > 0.f ? v : (expf(v) - 1.f);  // ELU alpha=1
    g_h[i * 64 + c] = v;
    if (do_pool) {
        int g = batch[i];
        atomicAdd(&g_pool[g * 64 + c], v);
        if (c == 0) atomicAdd(&g_pcnt[g], 1.f);
    }
}

// ---------------- head: mean-pool divide -> fc1 -> relu -> bn -> fc3 ----------------
__global__ void head_kernel(const float* __restrict__ Wfc1, const float* __restrict__ bfc1,
                            const float* __restrict__ gam, const float* __restrict__ bet,
                            const float* __restrict__ mean, const float* __restrict__ var,
                            const float* __restrict__ Wfc3, const float* __restrict__ bfc3,
                            float* __restrict__ out) {
    int g = threadIdx.x;
    if (g >= GG) return;
    float inv_cnt = 1.0f / fmaxf(g_pcnt[g], 1.0f);
    float pooled[64];
#pragma unroll
    for (int c = 0; c < 64; c++) pooled[c] = g_pool[g * 64 + c] * inv_cnt;
    float acc = bfc3[0];
    for (int j = 0; j < 32; j++) {
        float z = bfc1[j];
#pragma unroll
        for (int c = 0; c < 64; c++) z = fmaf(pooled[c], Wfc1[c * 32 + j], z);
        z = fmaxf(z, 0.f);
        z = (z - mean[j]) * rsqrtf(var[j] + 1e-5f) * gam[j] + bet[j];
        acc = fmaf(z, Wfc3[j], acc);
    }
    out[g] = acc;
}

// ---------------- launch ----------------
extern "C" void kernel_launch(void* const* d_in, const int* in_sizes, int n_in,
                              void* d_out, int out_size) {
    const float* x = (const float*)d_in[0];
    const int* ei = (const int*)d_in[1];
    const float* ea = (const float*)d_in[2];
    const int* batch = (const int*)d_in[3];
    const float* Wl1 = (const float*)d_in[4];
    const float* bl1 = (const float*)d_in[5];
    const float* Wr1 = (const float*)d_in[6];
    const float* br1 = (const float*)d_in[7];
    const float* We1 = (const float*)d_in[8];
    const float* att1 = (const float*)d_in[9];
    const float* bias1 = (const float*)d_in[10];
    const float* Wl2 = (const float*)d_in[11];
    const float* bl2 = (const float*)d_in[12];
    const float* Wr2 = (const float*)d_in[13];
    const float* br2 = (const float*)d_in[14];
    const float* We2 = (const float*)d_in[15];
    const float* att2 = (const float*)d_in[16];
    const float* bias2 = (const float*)d_in[17];
    const float* Wfc1 = (const float*)d_in[18];
    const float* bfc1 = (const float*)d_in[19];
    const float* bng = (const float*)d_in[20];
    const float* bnb = (const float*)d_in[21];
    const float* bnm = (const float*)d_in[22];
    const float* bnv = (const float*)d_in[23];
    const float* Wfc3 = (const float*)d_in[24];
    const float* bfc3 = (const float*)d_in[25];
    float* out = (float*)d_out;

    const int edge_grid = (EP * 32 + 255) / 256;

    // self-loop mean attrs
    init_graph_kernel<<<(NN + 255) / 256, 256>>>();
    loop_accum_kernel<<<(EE + 255) / 256, 256>>>(ei, ea);
    loop_final_kernel<<<(NN + 255) / 256, 256>>>();

    // ---- GATv2 layer 1 ----
    init_layer_kernel<<<(NN * HIDD + 255) / 256, 256>>>();
    linear_kernel<128, false><<<(NN + 3) / 4, dim3(64, 4)>>>(x, Wl1, bl1, Wr1, br1);
    edge_logits_kernel<<<edge_grid, 256>>>(ei, ea, We1, att1);
    edge_accum_kernel<<<edge_grid, 256>>>(ei);
    node_final_kernel<<<NN, 64>>>(bias1, batch, 0);

    // ---- GATv2 layer 2 ----
    init_layer_kernel<<<(NN * HIDD + 255) / 256, 256>>>();
    linear_kernel<64, true><<<(NN + 3) / 4, dim3(64, 4)>>>(nullptr, Wl2, bl2, Wr2, br2);
    edge_logits_kernel<<<edge_grid, 256>>>(ei, ea, We2, att2);
    edge_accum_kernel<<<edge_grid, 256>>>(ei);
    node_final_kernel<<<NN, 64>>>(bias2, batch, 1);

    // ---- head ----
    head_kernel<<<1, 64>>>(Wfc1, bfc1, bng, bnb, bnm, bnv, Wfc3, bfc3, out);
}

// round 6
// speedup vs baseline: 2.0851x; 2.0851x over previous
#include <cuda_runtime.h>
#include <math_constants.h>

#define NN 50000
#define EE 1600000
#define EP (EE + NN)
#define GG 64
#define IND 128
#define HIDD 64
#define SCAN_BLK 1024
#define NBLK ((NN + SCAN_BLK - 1) / SCAN_BLK)

// ---------------- device scratch (no allocations allowed) ----------------
__device__ __align__(16) float g_xl[NN * HIDD];
__device__ __align__(16) float g_xr[NN * HIDD];
__device__ __align__(16) float g_h[NN * HIDD];
__device__ int g_deg[NN];        // in-degree incl. self loop
__device__ int g_off[NN + 1];    // CSR offsets (exclusive)
__device__ int g_cur[NN];        // scatter cursors
__device__ int g_csr_src[EP];    // src node per CSR slot
__device__ float g_csr_a[EP];    // edge attr per CSR slot
__device__ int g_bsum[NBLK + 1]; // scan block sums
__device__ float g_pool[GG * HIDD];
__device__ float g_pcnt[GG];

// ---------------- init ----------------
__global__ void init_kernel() {
    int i = blockIdx.x * blockDim.x + threadIdx.x;
    if (i < NN) { g_deg[i] = 1; g_cur[i] = 1; }   // slot 0 = self loop
    if (i < GG * HIDD) g_pool[i] = 0.f;
    if (i < GG) g_pcnt[i] = 0.f;
}

// ---------------- CSR build ----------------
__global__ void count_kernel(const int* __restrict__ ei) {
    int e = blockIdx.x * blockDim.x + threadIdx.x;
    if (e >= EE) return;
    atomicAdd(&g_deg[ei[EE + e]], 1);
}

// per-block inclusive scan (Hillis-Steele) of degrees -> g_off (temp = inclusive-within-block)
__global__ void scan1_kernel() {
    __shared__ int s[SCAN_BLK];
    int t = threadIdx.x;
    int i = blockIdx.x * SCAN_BLK + t;
    int v = (i < NN) ? g_deg[i] : 0;
    s[t] = v;
    __syncthreads();
#pragma unroll
    for (int o = 1; o < SCAN_BLK; o <<= 1) {
        int x = (t >= o) ? s[t - o] : 0;
        __syncthreads();
        s[t] += x;
        __syncthreads();
    }
    if (i < NN) g_off[i] = s[t];
    if (t == SCAN_BLK - 1) g_bsum[blockIdx.x] = s[t];
}

__global__ void scan2_kernel() {
    if (threadIdx.x == 0) {
        int run = 0;
        for (int b = 0; b < NBLK; b++) { int v = g_bsum[b]; g_bsum[b] = run; run += v; }
    }
}

__global__ void scan3_kernel() {
    int i = blockIdx.x * SCAN_BLK + threadIdx.x;
    if (i < NN) g_off[i] = g_off[i] - g_deg[i] + g_bsum[blockIdx.x];
    if (i == 0) g_off[NN] = EP;
}

__global__ void scatter_kernel(const int* __restrict__ ei, const float* __restrict__ ea) {
    int e = blockIdx.x * blockDim.x + threadIdx.x;
    if (e >= EE) return;
    int d = ei[EE + e];
    int pos = g_off[d] + atomicAdd(&g_cur[d], 1);
    g_csr_src[pos] = ei[e];
    g_csr_a[pos] = ea[e];
}

// self-loop attr = mean of real incoming edge attrs; warp per node
__global__ void selfloop_kernel() {
    int gtid = blockIdx.x * blockDim.x + threadIdx.x;
    int node = gtid >> 5, lane = gtid & 31;
    if (node >= NN) return;
    int beg = g_off[node], end = g_off[node + 1];
    float s = 0.f;
    for (int p = beg + 1 + lane; p < end; p += 32) s += g_csr_a[p];
#pragma unroll
    for (int o = 16; o; o >>= 1) s += __shfl_xor_sync(0xffffffffu, s, o);
    if (lane == 0) {
        int cnt = end - beg - 1;
        g_csr_a[beg] = s / fmaxf((float)cnt, 1.f);
        g_csr_src[beg] = node;
    }
}

// ---------------- node linear transforms: xl = h@Wl+bl, xr = h@Wr+br ----------------
template <int K, bool FROM_H>
__global__ void linear_kernel(const float* __restrict__ x,
                              const float* __restrict__ Wl, const float* __restrict__ bl,
                              const float* __restrict__ Wr, const float* __restrict__ br) {
    __shared__ float sx[4][K];
    int node = blockIdx.x * 4 + threadIdx.y;
    int c = threadIdx.x;
    if (node < NN) {
        const float* src = FROM_H ? (g_h + node * K) : (x + node * K);
        for (int k = c; k < K; k += 64) sx[threadIdx.y][k] = src[k];
    }
    __syncthreads();
    if (node >= NN) return;
    float al = bl[c], ar = br[c];
#pragma unroll 8
    for (int k = 0; k < K; k++) {
        float xv = sx[threadIdx.y][k];
        al = fmaf(xv, Wl[k * 64 + c], al);
        ar = fmaf(xv, Wr[k * 64 + c], ar);
    }
    g_xl[node * 64 + c] = al;
    g_xr[node * 64 + c] = ar;
}

// ---------------- fused GAT aggregation: warp per node, online softmax ----------------
// Single pass over the node's edges: gather xl[src] once, compute logit via warp
// butterfly, maintain running (max, denom, numerator) with rescaling.
__global__ void gat_node_kernel(const float* __restrict__ We, const float* __restrict__ att,
                                const float* __restrict__ bias, const int* __restrict__ batch,
                                int do_pool) {
    int gtid = blockIdx.x * blockDim.x + threadIdx.x;
    int node = gtid >> 5, lane = gtid & 31;
    if (node >= NN) return;
    int beg = g_off[node], end = g_off[node + 1];

    float2 xr2 = ((const float2*)g_xr)[node * 32 + lane];
    float2 w = ((const float2*)We)[lane];
    float2 at = ((const float2*)att)[lane];

    float m = -CUDART_INF_F;
    float den = 0.f;
    float accx = 0.f, accy = 0.f;

#pragma unroll 2
    for (int p = beg; p < end; p++) {
        int s = __ldg(&g_csr_src[p]);      // broadcast
        float a = __ldg(&g_csr_a[p]);      // broadcast
        float2 xl = ((const float2*)g_xl)[s * 32 + lane];
        float v0 = xl.x + xr2.x + a * w.x;
        v0 = v0 > 0.f ? v0 : 0.2f * v0;
        float v1 = xl.y + xr2.y + a * w.y;
        v1 = v1 > 0.f ? v1 : 0.2f * v1;
        float sum = v0 * at.x + v1 * at.y;
#pragma unroll
        for (int o = 16; o; o >>= 1) sum += __shfl_xor_sync(0xffffffffu, sum, o);
        // online softmax update (all lanes have identical sum/m/den)
        float mn = fmaxf(m, sum);
        float scale = __expf(m - mn);      // 1.0f when max unchanged
        float pe = __expf(sum - mn);
        accx = accx * scale + pe * xl.x;
        accy = accy * scale + pe * xl.y;
        den = den * scale + pe;
        m = mn;
    }

    float inv = 1.f / (den + 1e-16f);
    float v0 = accx * inv + bias[2 * lane];
    v0 = v0 > 0.f ? v0 : (expf(v0) - 1.f);   // ELU
    float v1 = accy * inv + bias[2 * lane + 1];
    v1 = v1 > 0.f ? v1 : (expf(v1) - 1.f);
    ((float2*)g_h)[node * 32 + lane] = make_float2(v0, v1);

    if (do_pool) {
        int g = batch[node];
        atomicAdd(&g_pool[g * 64 + 2 * lane], v0);
        atomicAdd(&g_pool[g * 64 + 2 * lane + 1], v1);
        if (lane == 0) atomicAdd(&g_pcnt[g], 1.f);
    }
}

// ---------------- head: mean-pool divide -> fc1 -> relu -> bn -> fc3 ----------------
__global__ void head_kernel(const float* __restrict__ Wfc1, const float* __restrict__ bfc1,
                            const float* __restrict__ gam, const float* __restrict__ bet,
                            const float* __restrict__ mean, const float* __restrict__ var,
                            const float* __restrict__ Wfc3, const float* __restrict__ bfc3,
                            float* __restrict__ out) {
    int g = threadIdx.x;
    if (g >= GG) return;
    float inv_cnt = 1.0f / fmaxf(g_pcnt[g], 1.0f);
    float pooled[64];
#pragma unroll
    for (int c = 0; c < 64; c++) pooled[c] = g_pool[g * 64 + c] * inv_cnt;
    float acc = bfc3[0];
    for (int j = 0; j < 32; j++) {
        float z = bfc1[j];
#pragma unroll
        for (int c = 0; c < 64; c++) z = fmaf(pooled[c], Wfc1[c * 32 + j], z);
        z = fmaxf(z, 0.f);
        z = (z - mean[j]) * rsqrtf(var[j] + 1e-5f) * gam[j] + bet[j];
        acc = fmaf(z, Wfc3[j], acc);
    }
    out[g] = acc;
}

// ---------------- launch ----------------
extern "C" void kernel_launch(void* const* d_in, const int* in_sizes, int n_in,
                              void* d_out, int out_size) {
    const float* x = (const float*)d_in[0];
    const int* ei = (const int*)d_in[1];
    const float* ea = (const float*)d_in[2];
    const int* batch = (const int*)d_in[3];
    const float* Wl1 = (const float*)d_in[4];
    const float* bl1 = (const float*)d_in[5];
    const float* Wr1 = (const float*)d_in[6];
    const float* br1 = (const float*)d_in[7];
    const float* We1 = (const float*)d_in[8];
    const float* att1 = (const float*)d_in[9];
    const float* bias1 = (const float*)d_in[10];
    const float* Wl2 = (const float*)d_in[11];
    const float* bl2 = (const float*)d_in[12];
    const float* Wr2 = (const float*)d_in[13];
    const float* br2 = (const float*)d_in[14];
    const float* We2 = (const float*)d_in[15];
    const float* att2 = (const float*)d_in[16];
    const float* bias2 = (const float*)d_in[17];
    const float* Wfc1 = (const float*)d_in[18];
    const float* bfc1 = (const float*)d_in[19];
    const float* bng = (const float*)d_in[20];
    const float* bnb = (const float*)d_in[21];
    const float* bnm = (const float*)d_in[22];
    const float* bnv = (const float*)d_in[23];
    const float* Wfc3 = (const float*)d_in[24];
    const float* bfc3 = (const float*)d_in[25];
    float* out = (float*)d_out;

    const int node_warp_grid = (NN * 32 + 255) / 256;

    // ---- CSR build (dst-sorted) ----
    init_kernel<<<(NN + 255) / 256, 256>>>();
    count_kernel<<<(EE + 255) / 256, 256>>>(ei);
    scan1_kernel<<<NBLK, SCAN_BLK>>>();
    scan2_kernel<<<1, 32>>>();
    scan3_kernel<<<NBLK, SCAN_BLK>>>();
    scatter_kernel<<<(EE + 255) / 256, 256>>>(ei, ea);
    selfloop_kernel<<<node_warp_grid, 256>>>();

    // ---- GATv2 layer 1 ----
    linear_kernel<128, false><<<(NN + 3) / 4, dim3(64, 4)>>>(x, Wl1, bl1, Wr1, br1);
    gat_node_kernel<<<node_warp_grid, 256>>>(We1, att1, bias1, batch, 0);

    // ---- GATv2 layer 2 ----
    linear_kernel<64, true><<<(NN + 3) / 4, dim3(64, 4)>>>(nullptr, Wl2, bl2, Wr2, br2);
    gat_node_kernel<<<node_warp_grid, 256>>>(We2, att2, bias2, batch, 1);

    // ---- head ----
    head_kernel<<<1, 64>>>(Wfc1, bfc1, bng, bnb, bnm, bnv, Wfc3, bfc3, out);
}